// round 7
// baseline (speedup 1.0000x reference)
#include <cuda_runtime.h>
#include <cuda_fp16.h>
#include <mma.h>
#include <math.h>

using namespace nvcuda;

#define NN   50000
#define EE   1600000
#define ET   (EE + NN)
#define INC  256
#define HC   128
#define HH   4
#define CC   32
#define OUTC 64
#define SCAN_BLKS ((NN + 255) / 256)   // 196

// ---------------- scratch (device globals) ------------------------------------
__device__ __align__(16) __half g_xh[(size_t)NN * INC];     // 25.6 MB fp16 x
__device__ __align__(16) __half g_hh[(size_t)NN * HC];      // 12.8 MB fp16 h
__device__ __align__(16) float g_asrc[(size_t)NN * HH];
__device__ __align__(16) float g_adst[(size_t)NN * HH];
__device__ __align__(16) float g_agg[(size_t)NN * HC];      // 25.6 MB
__device__            int   g_deg[NN];
__device__            int   g_off[NN + 1];
__device__            int   g_cur[NN];
__device__            int   g_bsum[SCAN_BLKS];
__device__            int   g_csr[ET];                       // 6.6 MB

// ---------------- helpers ----------------------------------------------------
__device__ __forceinline__ float leaky(float v) {
    return v >= 0.0f ? v : 0.2f * v;
}
__device__ __forceinline__ int clampN(int v) {
    return v < 0 ? 0 : (v >= NN ? NN - 1 : v);
}

// ---------------- K0: x fp32 -> fp16 (+ deg init) -----------------------------
__global__ void k_cvt(const float* __restrict__ x) {
    int i = blockIdx.x * blockDim.x + threadIdx.x;     // one per 8 elems
    if (i < NN * INC / 8) {
        float4 a = *(const float4*)&x[(size_t)i * 8];
        float4 b = *(const float4*)&x[(size_t)i * 8 + 4];
        __half2 h0 = __floats2half2_rn(a.x, a.y);
        __half2 h1 = __floats2half2_rn(a.z, a.w);
        __half2 h2 = __floats2half2_rn(b.x, b.y);
        __half2 h3 = __floats2half2_rn(b.z, b.w);
        uint4 v;
        v.x = *(unsigned*)&h0; v.y = *(unsigned*)&h1;
        v.z = *(unsigned*)&h2; v.w = *(unsigned*)&h3;
        *(uint4*)&g_xh[(size_t)i * 8] = v;
    }
    if (i < NN) g_deg[i] = 1;
}

// ---------------- K1: h = x @ W via WMMA + fused attention --------------------
// block = 256 threads (8 warps). Block tile: 128 rows. Warp strip: 16 rows x 128 cols.
__global__ void __launch_bounds__(256) k_gemm1t(
        const float* __restrict__ W,
        const float* __restrict__ att_src, const float* __restrict__ att_dst) {
    __shared__ __half xs[128][16];          // 4 KB  (row-major, ld=16)
    __shared__ __half wsb[16][128];         // 4 KB  (row-major, ld=128)
    __shared__ float  stage[8][16][20];     // 10 KB per-warp epilogue staging (ldm=20, mult of 4)

    const int t    = threadIdx.x;
    const int warp = t >> 5;
    const int lane = t & 31;
    const int row0 = blockIdx.x * 128;
    const int wrow = row0 + warp * 16;

    wmma::fragment<wmma::accumulator, 16, 16, 16, float> acc[8];
#pragma unroll
    for (int j = 0; j < 8; j++) wmma::fill_fragment(acc[j], 0.0f);

    for (int kt = 0; kt < 16; kt++) {
        // x tile: 128 rows x 16 k halves. 256 threads: 2 per row, 8 halves each.
        {
            int r  = t >> 1;
            int hp = t & 1;
            int gr = row0 + r; if (gr >= NN) gr = NN - 1;
            *(uint4*)&xs[r][hp * 8] =
                *(const uint4*)&g_xh[(size_t)gr * INC + kt * 16 + hp * 8];
        }
        // W tile: 16 k x 128 cols, fp32->fp16 convert. 256 threads x 8 elems.
        {
            int r = t >> 4;
            int g = t & 15;
            const float4* wp = (const float4*)&W[(size_t)(kt * 16 + r) * HC + g * 8];
            float4 a = wp[0], b = wp[1];
            __half2 h0 = __floats2half2_rn(a.x, a.y);
            __half2 h1 = __floats2half2_rn(a.z, a.w);
            __half2 h2 = __floats2half2_rn(b.x, b.y);
            __half2 h3 = __floats2half2_rn(b.z, b.w);
            uint4 v;
            v.x = *(unsigned*)&h0; v.y = *(unsigned*)&h1;
            v.z = *(unsigned*)&h2; v.w = *(unsigned*)&h3;
            *(uint4*)&wsb[r][g * 8] = v;
        }
        __syncthreads();

        wmma::fragment<wmma::matrix_a, 16, 16, 16, __half, wmma::row_major> af;
        wmma::load_matrix_sync(af, &xs[warp * 16][0], 16);
#pragma unroll
        for (int j = 0; j < 8; j++) {
            wmma::fragment<wmma::matrix_b, 16, 16, 16, __half, wmma::row_major> bf;
            wmma::load_matrix_sync(bf, &wsb[0][j * 16], 128);
            wmma::mma_sync(acc[j], af, bf, acc[j]);
        }
        __syncthreads();
    }

    // Epilogue: per 16-col tile, stage fp32 -> (attention partial, fp16 h store)
    const int lrow = lane >> 1;             // 0..15
    const int lhp  = lane & 1;              // col half (8 cols)
    const int grow = wrow + lrow;
    float sS[4] = {0.f, 0.f, 0.f, 0.f};
    float sD[4] = {0.f, 0.f, 0.f, 0.f};

#pragma unroll
    for (int j = 0; j < 8; j++) {
        wmma::store_matrix_sync(&stage[warp][0][0], acc[j], 20, wmma::mem_row_major);
        __syncwarp();
        int c8 = j * 2 + lhp;               // 8-col group index 0..15
        int hd = c8 >> 2;                   // head
        const float* sp = &stage[warp][lrow][lhp * 8];
        float4 v0 = make_float4(sp[0], sp[1], sp[2], sp[3]);
        float4 v1 = make_float4(sp[4], sp[5], sp[6], sp[7]);
        float4 aS0 = *(const float4*)&att_src[c8 * 8];
        float4 aS1 = *(const float4*)&att_src[c8 * 8 + 4];
        float4 aD0 = *(const float4*)&att_dst[c8 * 8];
        float4 aD1 = *(const float4*)&att_dst[c8 * 8 + 4];
        sS[hd] += v0.x * aS0.x + v0.y * aS0.y + v0.z * aS0.z + v0.w * aS0.w
                + v1.x * aS1.x + v1.y * aS1.y + v1.z * aS1.z + v1.w * aS1.w;
        sD[hd] += v0.x * aD0.x + v0.y * aD0.y + v0.z * aD0.z + v0.w * aD0.w
                + v1.x * aD1.x + v1.y * aD1.y + v1.z * aD1.z + v1.w * aD1.w;
        if (grow < NN) {
            __half2 p0 = __floats2half2_rn(v0.x, v0.y);
            __half2 p1 = __floats2half2_rn(v0.z, v0.w);
            __half2 p2 = __floats2half2_rn(v1.x, v1.y);
            __half2 p3 = __floats2half2_rn(v1.z, v1.w);
            uint4 pv;
            pv.x = *(unsigned*)&p0; pv.y = *(unsigned*)&p1;
            pv.z = *(unsigned*)&p2; pv.w = *(unsigned*)&p3;
            *(uint4*)&g_hh[(size_t)grow * HC + c8 * 8] = pv;
        }
        __syncwarp();
    }
    // combine the two col-half lanes of each row
    const unsigned FULL = 0xffffffffu;
#pragma unroll
    for (int hd = 0; hd < 4; hd++) {
        sS[hd] += __shfl_xor_sync(FULL, sS[hd], 1);
        sD[hd] += __shfl_xor_sync(FULL, sD[hd], 1);
    }
    if (lhp == 0 && grow < NN) {
        float4 vs = make_float4(sS[0], sS[1], sS[2], sS[3]);
        float4 vd = make_float4(sD[0], sD[1], sD[2], sD[3]);
        *(float4*)&g_asrc[(size_t)grow * 4] = vs;
        *(float4*)&g_adst[(size_t)grow * 4] = vd;
    }
}

// ---------------- CSR build ---------------------------------------------------
__global__ void k_hist(const int* __restrict__ ei) {
    int i = blockIdx.x * blockDim.x + threadIdx.x;
    if (i >= EE) return;
    atomicAdd(&g_deg[clampN(ei[EE + i])], 1);
}

__global__ void k_scanA() {
    __shared__ int sh[256];
    int t = threadIdx.x;
    int idx = blockIdx.x * 256 + t;
    int v = (idx < NN) ? g_deg[idx] : 0;
    sh[t] = v;
    __syncthreads();
#pragma unroll
    for (int o = 1; o < 256; o <<= 1) {
        int u = (t >= o) ? sh[t - o] : 0;
        __syncthreads();
        sh[t] += u;
        __syncthreads();
    }
    if (idx < NN) g_off[idx] = sh[t] - v;
    if (t == 255) g_bsum[blockIdx.x] = sh[255];
}

__global__ void k_scanB() {
    __shared__ int sh[SCAN_BLKS];
    int t = threadIdx.x;
    int v = (t < SCAN_BLKS) ? g_bsum[t] : 0;
    if (t < SCAN_BLKS) sh[t] = v;
    __syncthreads();
    for (int o = 1; o < SCAN_BLKS; o <<= 1) {
        int u = (t >= o && t < SCAN_BLKS) ? sh[t - o] : 0;
        __syncthreads();
        if (t < SCAN_BLKS) sh[t] += u;
        __syncthreads();
    }
    if (t < SCAN_BLKS) g_bsum[t] = sh[t] - v;
}

__global__ void k_prep() {
    int n = blockIdx.x * blockDim.x + threadIdx.x;
    if (n >= NN) return;
    int off = g_off[n] + g_bsum[n >> 8];
    g_off[n] = off;
    g_csr[off] = n;          // self loop first
    g_cur[n] = off + 1;
    if (n == 0) g_off[NN] = ET;
}

__global__ void k_scatter(const int* __restrict__ ei) {
    int i = blockIdx.x * blockDim.x + threadIdx.x;
    if (i >= EE) return;
    int s = clampN(ei[i]);
    int d = clampN(ei[EE + i]);
    int pos = atomicAdd(&g_cur[d], 1);
    g_csr[pos] = s;
}

// ---------------- K6: fused softmax + aggregation (warp per dst, fp16 gather) --
__global__ void k_aggr() {
    int w = (int)((blockIdx.x * (size_t)blockDim.x + threadIdx.x) >> 5);
    if (w >= NN) return;
    int lane = threadIdx.x & 31;
    int hd = lane >> 3;

    int beg = g_off[w];
    int end = g_off[w + 1];
    float adh = g_adst[(size_t)w * 4 + hd];

    float4 acc = make_float4(0.f, 0.f, 0.f, 0.f);
    float den = 0.f;

    for (int p = beg; p < end; p += 32) {
        int cnt = end - p; if (cnt > 32) cnt = 32;
        int src = (lane < cnt) ? g_csr[p + lane] : 0;
#pragma unroll 4
        for (int j = 0; j < cnt; j++) {
            int s = __shfl_sync(0xffffffffu, src, j);
            float e  = leaky(g_asrc[(size_t)s * 4 + hd] + adh);
            float ex = __expf(e);
            uint2 hv = *(const uint2*)&g_hh[(size_t)s * HC + lane * 4];
            float2 f0 = __half22float2(*(__half2*)&hv.x);
            float2 f1 = __half22float2(*(__half2*)&hv.y);
            acc.x += ex * f0.x;
            acc.y += ex * f0.y;
            acc.z += ex * f1.x;
            acc.w += ex * f1.y;
            den += ex;
        }
    }
    float inv = 1.0f / den;
    acc.x *= inv; acc.y *= inv; acc.z *= inv; acc.w *= inv;
    *(float4*)&g_agg[(size_t)w * HC + lane * 4] = acc;
}

// ---------------- K7: out = elu(agg + bias) @ lin_W + lin_b ------------------
__global__ void k_out(const float* __restrict__ bias, const float* __restrict__ lin_W,
                      const float* __restrict__ lin_b, float* __restrict__ out) {
    __shared__ float ws[HC * OUTC];
    __shared__ float bs[HC];
    __shared__ float lb[OUTC];
    int t = threadIdx.x;
    for (int i = t; i < HC * OUTC / 4; i += 256)
        ((float4*)ws)[i] = ((const float4*)lin_W)[i];
    if (t < HC)   bs[t] = bias[t];
    if (t < OUTC) lb[t] = lin_b[t];
    __syncthreads();

    int warp = t >> 5, lane = t & 31;
    for (int r = blockIdx.x * 8 + warp; r < NN; r += gridDim.x * 8) {
        float acc0 = 0.f, acc1 = 0.f;
#pragma unroll
        for (int kb = 0; kb < 4; kb++) {
            int k = kb * 32 + lane;
            float v = g_agg[(size_t)r * HC + k] + bs[k];
            v = v > 0.f ? v : expm1f(v);
#pragma unroll
            for (int j = 0; j < 32; j++) {
                float a = __shfl_sync(0xffffffffu, v, j);
                int kk = kb * 32 + j;
                acc0 += a * ws[kk * OUTC + lane];
                acc1 += a * ws[kk * OUTC + 32 + lane];
            }
        }
        out[(size_t)r * OUTC + lane]      = acc0 + lb[lane];
        out[(size_t)r * OUTC + 32 + lane] = acc1 + lb[lane + 32];
    }
}

// ---------------- launch ------------------------------------------------------
extern "C" void kernel_launch(void* const* d_in, const int* in_sizes, int n_in,
                              void* d_out, int out_size) {
    const float* x       = (const float*)d_in[0];
    const int*   eidx    = (const int*)d_in[1];
    const float* W       = (const float*)d_in[2];
    const float* att_src = (const float*)d_in[3];
    const float* att_dst = (const float*)d_in[4];
    const float* bias    = (const float*)d_in[5];
    const float* lin_W   = (const float*)d_in[6];
    const float* lin_b   = (const float*)d_in[7];
    float*       out     = (float*)d_out;

    k_cvt    <<<(NN * INC / 8 + 255) / 256, 256>>>(x);
    k_gemm1t <<<(NN + 127) / 128, 256>>>(W, att_src, att_dst);
    k_hist   <<<(EE + 255) / 256, 256>>>(eidx);
    k_scanA  <<<SCAN_BLKS, 256>>>();
    k_scanB  <<<1, 256>>>();
    k_prep   <<<(NN + 255) / 256, 256>>>();
    k_scatter<<<(EE + 255) / 256, 256>>>(eidx);
    k_aggr   <<<(NN * 32 + 255) / 256, 256>>>();
    k_out    <<<625, 256>>>(bias, lin_W, lin_b, out);
}